// round 2
// baseline (speedup 1.0000x reference)
#include <cuda_runtime.h>
#include <math.h>

#define NN 50000
#define NE 150000
#define DD 128
#define NH 4
#define HDIM 512
#define EDIM 16
#define PC 2304
#define OFF_XR 0
#define OFF_Q 128
#define OFF_K 640
#define OFF_V 1152
#define OFF_SK 1664
#define OFF_G 1792

// ---------------- scratch (static device globals; no dynamic alloc) ----------------
__device__ float g_proj[(size_t)NN * PC];      // xr | q | k | v | skip | g
__device__ float g_wcat[DD * PC];
__device__ float g_bcat[PC];
__device__ float g_mean[NN * DD];              // neighbor sum -> mean
__device__ float g_cnt[NN];
__device__ float g_ms[NN * DD];                // mean @ Wl + sage_b
__device__ float g_as[NN * NH];
__device__ float g_ad[NN * NH];
__device__ float g_logT[NE * NH];
__device__ float g_expT[NE * NH];
__device__ int   g_maxT[NN * NH];
__device__ float g_sumT[NN * NH];
__device__ float g_outT[(size_t)NN * HDIM];
__device__ float g_logG[(NE + NN) * NH];
__device__ float g_expG[(NE + NN) * NH];
__device__ int   g_maxG[NN * NH];
__device__ float g_sumG[NN * NH];
__device__ float g_outG[(size_t)NN * HDIM];
__device__ float g_cat[(size_t)NN * 3 * DD];
__device__ float g_fus[NN * DD];

// ---------------- helpers ----------------
__device__ __forceinline__ int f2i_ord(float f) {
    int i = __float_as_int(f);
    return (i < 0) ? (i ^ 0x7fffffff) : i;
}
__device__ __forceinline__ float i2f_ord(int i) {
    return __int_as_float((i < 0) ? (i ^ 0x7fffffff) : i);
}
__device__ __forceinline__ float warpSum(float v) {
#pragma unroll
    for (int o = 16; o; o >>= 1) v += __shfl_xor_sync(0xffffffffu, v, o);
    return v;
}
__device__ __forceinline__ float blockSum128(float v) {
    __shared__ float red[4];
    v = warpSum(v);
    int w = threadIdx.x >> 5;
    if ((threadIdx.x & 31) == 0) red[w] = v;
    __syncthreads();
    float r = red[0] + red[1] + red[2] + red[3];
    __syncthreads();
    return r;
}

// ---------------- weight packing ----------------
__global__ void k_pack(const float* __restrict__ Wr, const float* __restrict__ tq,
                       const float* __restrict__ tk, const float* __restrict__ tv,
                       const float* __restrict__ tsk, const float* __restrict__ gat,
                       const float* __restrict__ qb, const float* __restrict__ kb,
                       const float* __restrict__ vb, const float* __restrict__ skb) {
    int t = blockIdx.x * blockDim.x + threadIdx.x;
    if (t >= DD * PC) return;
    int r = t / PC, c = t % PC;
    float v;
    if (c < 128)       v = Wr[r * 128 + c];
    else if (c < 640)  v = tq[r * 512 + (c - 128)];
    else if (c < 1152) v = tk[r * 512 + (c - 640)];
    else if (c < 1664) v = tv[r * 512 + (c - 1152)];
    else if (c < 1792) v = tsk[r * 128 + (c - 1664)];
    else               v = gat[r * 512 + (c - 1792)];
    g_wcat[t] = v;
    if (r == 0) {
        float b;
        if (c < 128)       b = 0.f;
        else if (c < 640)  b = qb[c - 128];
        else if (c < 1152) b = kb[c - 640];
        else if (c < 1664) b = vb[c - 1152];
        else if (c < 1792) b = skb[c - 1664];
        else               b = 0.f;
        g_bcat[c] = b;
    }
}

// ---------------- init ----------------
__global__ void k_init() {
    int t = blockIdx.x * blockDim.x + threadIdx.x;
    if (t < NN * HDIM) { g_outT[t] = 0.f; g_outG[t] = 0.f; }
    if (t < NN * DD) g_mean[t] = 0.f;
    if (t < NN) g_cnt[t] = 0.f;
    if (t < NN * NH) {
        g_sumT[t] = 0.f; g_sumG[t] = 0.f;
        g_maxT[t] = 0x80000000; g_maxG[t] = 0x80000000;
    }
}

// ---------------- SGEMM 128x128x8, 256 threads, 8x8 per thread ----------------
__global__ __launch_bounds__(256) void sgemm128(
    const float* __restrict__ A, const float* __restrict__ B,
    const float* __restrict__ bias, float* __restrict__ C,
    int M, int Ncol, int K) {
    __shared__ float As[8][128];
    __shared__ float Bs[8][128];
    int tid = threadIdx.x;
    int tcol = tid & 15;
    int trow = tid >> 4;
    int rowBase = blockIdx.y * 128;
    int colBase = blockIdx.x * 128;
    float acc[8][8];
#pragma unroll
    for (int i = 0; i < 8; i++)
#pragma unroll
        for (int j = 0; j < 8; j++) acc[i][j] = 0.f;

    int aRow = tid >> 1;
    int aCol4 = (tid & 1) * 4;
    int bRow = tid >> 5;
    int bCol4 = (tid & 31) * 4;

    for (int k0 = 0; k0 < K; k0 += 8) {
        int gr = rowBase + aRow;
        float4 av = make_float4(0.f, 0.f, 0.f, 0.f);
        if (gr < M) av = *reinterpret_cast<const float4*>(A + (size_t)gr * K + k0 + aCol4);
        As[aCol4 + 0][aRow] = av.x;
        As[aCol4 + 1][aRow] = av.y;
        As[aCol4 + 2][aRow] = av.z;
        As[aCol4 + 3][aRow] = av.w;
        float4 bv = *reinterpret_cast<const float4*>(B + (size_t)(k0 + bRow) * Ncol + colBase + bCol4);
        *reinterpret_cast<float4*>(&Bs[bRow][bCol4]) = bv;
        __syncthreads();
#pragma unroll
        for (int kk = 0; kk < 8; kk++) {
            float4 a0 = *reinterpret_cast<const float4*>(&As[kk][trow * 4]);
            float4 a1 = *reinterpret_cast<const float4*>(&As[kk][64 + trow * 4]);
            float4 b0 = *reinterpret_cast<const float4*>(&Bs[kk][tcol * 4]);
            float4 b1 = *reinterpret_cast<const float4*>(&Bs[kk][64 + tcol * 4]);
            float a[8] = {a0.x, a0.y, a0.z, a0.w, a1.x, a1.y, a1.z, a1.w};
            float b[8] = {b0.x, b0.y, b0.z, b0.w, b1.x, b1.y, b1.z, b1.w};
#pragma unroll
            for (int i = 0; i < 8; i++)
#pragma unroll
                for (int j = 0; j < 8; j++) acc[i][j] += a[i] * b[j];
        }
        __syncthreads();
    }
#pragma unroll
    for (int i = 0; i < 8; i++) {
        int lr = (i < 4) ? (trow * 4 + i) : (64 + trow * 4 + i - 4);
        int gr = rowBase + lr;
        if (gr >= M) continue;
#pragma unroll
        for (int j = 0; j < 8; j++) {
            int lc = (j < 4) ? (tcol * 4 + j) : (64 + tcol * 4 + j - 4);
            int gc = colBase + lc;
            float v = acc[i][j];
            if (bias) v += bias[gc];
            C[(size_t)gr * Ncol + gc] = v;
        }
    }
}

// ---------------- SAGE ----------------
__global__ void k_sage_agg(const int* __restrict__ ei, const float* __restrict__ x) {
    int t = blockIdx.x * blockDim.x + threadIdx.x;
    if (t >= NE * DD) return;
    int e = t >> 7, d = t & 127;
    int src = ei[e], dst = ei[NE + e];
    atomicAdd(&g_mean[dst * DD + d], x[(size_t)src * DD + d]);
    if (d == 0) atomicAdd(&g_cnt[dst], 1.f);
}
__global__ void k_sage_mean() {
    int t = blockIdx.x * blockDim.x + threadIdx.x;
    if (t >= NN * DD) return;
    g_mean[t] /= fmaxf(g_cnt[t >> 7], 1.f);
}

// ---------------- GAT attention coefficients ----------------
__global__ void k_gat_coef(const float* __restrict__ att_src, const float* __restrict__ att_dst) {
    int n = blockIdx.x;
    int w = threadIdx.x >> 5, lane = threadIdx.x & 31;
    const float* grow = g_proj + (size_t)n * PC + OFF_G + w * DD;
    float s1 = 0.f, s2 = 0.f;
    for (int d = lane; d < DD; d += 32) {
        float gv = grow[d];
        s1 += gv * att_src[w * DD + d];
        s2 += gv * att_dst[w * DD + d];
    }
    s1 = warpSum(s1);
    s2 = warpSum(s2);
    if (lane == 0) { g_as[n * NH + w] = s1; g_ad[n * NH + w] = s2; }
}

// ---------------- Transformer: logits (warp per edge) ----------------
__global__ __launch_bounds__(256) void k_t_logits(const int* __restrict__ ei,
                                                  const float* __restrict__ ea,
                                                  const float* __restrict__ teW) {
    __shared__ float ws[EDIM * HDIM];
    for (int i = threadIdx.x; i < EDIM * HDIM; i += blockDim.x) ws[i] = teW[i];
    __syncthreads();
    int warpId = threadIdx.x >> 5, lane = threadIdx.x & 31;
    int e = blockIdx.x * 8 + warpId;
    int src = ei[e], dst = ei[NE + e];
    float eav = (lane < EDIM) ? ea[(size_t)e * EDIM + lane] : 0.f;
    const float* qrow = g_proj + (size_t)dst * PC + OFF_Q;
    const float* krow = g_proj + (size_t)src * PC + OFF_K;
#pragma unroll
    for (int h = 0; h < NH; h++) {
        float partial = 0.f;
        for (int d = lane; d < DD; d += 32) {
            int c = h * DD + d;
            float ev = 0.f;
#pragma unroll
            for (int j = 0; j < EDIM; j++)
                ev += __shfl_sync(0xffffffffu, eav, j) * ws[j * HDIM + c];
            partial += qrow[c] * (krow[c] + ev);
        }
        partial = warpSum(partial);
        if (lane == 0) {
            float lg = partial * 0.08838834764831845f;  // 1/sqrt(128)
            g_logT[e * NH + h] = lg;
            atomicMax(&g_maxT[dst * NH + h], f2i_ord(lg));
        }
    }
}

// ---------------- Transformer: exp + sum ----------------
__global__ void k_t_expsum(const int* __restrict__ ei) {
    int t = blockIdx.x * blockDim.x + threadIdx.x;
    if (t >= NE * NH) return;
    int e = t >> 2, h = t & 3;
    int dst = ei[NE + e];
    float m = i2f_ord(g_maxT[dst * NH + h]);
    float ex = expf(g_logT[t] - m);
    g_expT[t] = ex;
    atomicAdd(&g_sumT[dst * NH + h], ex);
}

// ---------------- Transformer: aggregate (warp per edge) ----------------
__global__ __launch_bounds__(256) void k_t_agg(const int* __restrict__ ei,
                                               const float* __restrict__ ea,
                                               const float* __restrict__ teW) {
    __shared__ float ws[EDIM * HDIM];
    for (int i = threadIdx.x; i < EDIM * HDIM; i += blockDim.x) ws[i] = teW[i];
    __syncthreads();
    int warpId = threadIdx.x >> 5, lane = threadIdx.x & 31;
    int e = blockIdx.x * 8 + warpId;
    int src = ei[e], dst = ei[NE + e];
    float eav = (lane < EDIM) ? ea[(size_t)e * EDIM + lane] : 0.f;
    const float* vrow = g_proj + (size_t)src * PC + OFF_V;
#pragma unroll
    for (int h = 0; h < NH; h++) {
        float alpha = g_expT[e * NH + h] / (g_sumT[dst * NH + h] + 1e-16f);
        for (int d = lane; d < DD; d += 32) {
            int c = h * DD + d;
            float ev = 0.f;
#pragma unroll
            for (int j = 0; j < EDIM; j++)
                ev += __shfl_sync(0xffffffffu, eav, j) * ws[j * HDIM + c];
            atomicAdd(&g_outT[(size_t)dst * HDIM + c], (vrow[c] + ev) * alpha);
        }
    }
}

// ---------------- GAT: logits (edges + self loops) ----------------
__global__ void k_g_logits(const int* __restrict__ ei) {
    int t = blockIdx.x * blockDim.x + threadIdx.x;
    if (t >= (NE + NN) * NH) return;
    int i = t >> 2, h = t & 3;
    int s, dd;
    if (i < NE) { s = ei[i]; dd = ei[NE + i]; }
    else { s = i - NE; dd = s; }
    float lg = g_as[s * NH + h] + g_ad[dd * NH + h];
    lg = (lg > 0.f) ? lg : 0.2f * lg;
    g_logG[t] = lg;
    atomicMax(&g_maxG[dd * NH + h], f2i_ord(lg));
}
__global__ void k_g_expsum(const int* __restrict__ ei) {
    int t = blockIdx.x * blockDim.x + threadIdx.x;
    if (t >= (NE + NN) * NH) return;
    int i = t >> 2, h = t & 3;
    int dd = (i < NE) ? ei[NE + i] : (i - NE);
    float m = i2f_ord(g_maxG[dd * NH + h]);
    float ex = expf(g_logG[t] - m);
    g_expG[t] = ex;
    atomicAdd(&g_sumG[dd * NH + h], ex);
}
// real edges only (self-loops folded into k_fuse_cat)
__global__ __launch_bounds__(256) void k_g_agg(const int* __restrict__ ei) {
    int warpId = threadIdx.x >> 5, lane = threadIdx.x & 31;
    int e = blockIdx.x * 8 + warpId;
    int src = ei[e], dst = ei[NE + e];
    const float* grow = g_proj + (size_t)src * PC + OFF_G;
#pragma unroll
    for (int h = 0; h < NH; h++) {
        float alpha = g_expG[e * NH + h] / (g_sumG[dst * NH + h] + 1e-16f);
        for (int d = lane; d < DD; d += 32) {
            int c = h * DD + d;
            atomicAdd(&g_outG[(size_t)dst * HDIM + c], grow[c] * alpha);
        }
    }
}

// ---------------- fusion: x_short/x_attn/x_nb -> gated cat ----------------
__global__ void k_fuse_cat(const float* __restrict__ gat_bias,
                           const float* __restrict__ gshort,
                           const float* __restrict__ gattn,
                           const float* __restrict__ gnb) {
    int t = blockIdx.x * blockDim.x + threadIdx.x;
    if (t >= NN * DD) return;
    int n = t >> 7, d = t & 127;
    const float* prow = g_proj + (size_t)n * PC;
    // SAGE branch
    float xs = fmaxf(g_ms[t] + prow[OFF_XR + d], 0.f);
    // Transformer branch
    float sT = 0.f;
#pragma unroll
    for (int h = 0; h < NH; h++) sT += g_outT[(size_t)n * HDIM + h * DD + d];
    float xa = fmaxf(sT * 0.25f + prow[OFF_SK + d], 0.f);
    // GAT branch (self-loop contribution added here)
    float sG = 0.f;
#pragma unroll
    for (int h = 0; h < NH; h++) {
        float aself = g_expG[(size_t)(NE + n) * NH + h] / (g_sumG[n * NH + h] + 1e-16f);
        sG += g_outG[(size_t)n * HDIM + h * DD + d] + prow[OFF_G + h * DD + d] * aself;
    }
    float xn = fmaxf(sG * 0.25f + gat_bias[d], 0.f);
    float gs = 1.f / (1.f + expf(-gshort[0]));
    float ga = 1.f / (1.f + expf(-gattn[0]));
    float gn = 1.f / (1.f + expf(-gnb[0]));
    g_cat[(size_t)n * 384 + d] = xs * gs;
    g_cat[(size_t)n * 384 + 128 + d] = xa * ga;
    g_cat[(size_t)n * 384 + 256 + d] = xn * gn;
}

// ---------------- final: LN(relu-free inner handled) ----------------
__global__ void k_final(const float* __restrict__ x,
                        const float* __restrict__ fus_g, const float* __restrict__ fus_b,
                        const float* __restrict__ norm_g, const float* __restrict__ norm_b,
                        float* __restrict__ out) {
    int n = blockIdx.x, d = threadIdx.x;
    float v = g_fus[n * DD + d];
    float m = blockSum128(v) * (1.f / 128.f);
    float c = v - m;
    float var = blockSum128(c * c) * (1.f / 128.f);
    float f = c * rsqrtf(var + 1e-5f) * fus_g[d] + fus_b[d];
    f = fmaxf(f, 0.f);
    float tsum = x[(size_t)n * DD + d] + f;
    float m2 = blockSum128(tsum) * (1.f / 128.f);
    float c2 = tsum - m2;
    float var2 = blockSum128(c2 * c2) * (1.f / 128.f);
    out[(size_t)n * DD + d] = c2 * rsqrtf(var2 + 1e-5f) * norm_g[d] + norm_b[d];
}

// ---------------- launcher ----------------
extern "C" void kernel_launch(void* const* d_in, const int* in_sizes, int n_in,
                              void* d_out, int out_size) {
    const float* x        = (const float*)d_in[0];
    const int*   ei       = (const int*)d_in[1];
    const float* ea       = (const float*)d_in[2];
    const float* sage_Wl  = (const float*)d_in[3];
    const float* sage_Wr  = (const float*)d_in[4];
    const float* sage_b   = (const float*)d_in[5];
    const float* tq_W     = (const float*)d_in[6];
    const float* tq_b     = (const float*)d_in[7];
    const float* tk_W     = (const float*)d_in[8];
    const float* tk_b     = (const float*)d_in[9];
    const float* tv_W     = (const float*)d_in[10];
    const float* tv_b     = (const float*)d_in[11];
    const float* te_W     = (const float*)d_in[12];
    const float* tskip_W  = (const float*)d_in[13];
    const float* tskip_b  = (const float*)d_in[14];
    const float* gat_W    = (const float*)d_in[15];
    const float* att_src  = (const float*)d_in[16];
    const float* att_dst  = (const float*)d_in[17];
    const float* gat_bias = (const float*)d_in[18];
    const float* gshort   = (const float*)d_in[19];
    const float* gattn    = (const float*)d_in[20];
    const float* gnb      = (const float*)d_in[21];
    const float* fus_W    = (const float*)d_in[22];
    const float* fus_b    = (const float*)d_in[23];
    const float* fus_g    = (const float*)d_in[24];
    const float* fus_beta = (const float*)d_in[25];
    const float* norm_g   = (const float*)d_in[26];
    const float* norm_b   = (const float*)d_in[27];
    float* out = (float*)d_out;

    float *p_proj, *p_wcat, *p_bcat, *p_mean, *p_ms, *p_cat, *p_fus;
    cudaGetSymbolAddress((void**)&p_proj, g_proj);
    cudaGetSymbolAddress((void**)&p_wcat, g_wcat);
    cudaGetSymbolAddress((void**)&p_bcat, g_bcat);
    cudaGetSymbolAddress((void**)&p_mean, g_mean);
    cudaGetSymbolAddress((void**)&p_ms, g_ms);
    cudaGetSymbolAddress((void**)&p_cat, g_cat);
    cudaGetSymbolAddress((void**)&p_fus, g_fus);

    k_pack<<<(DD * PC + 255) / 256, 256>>>(sage_Wr, tq_W, tk_W, tv_W, tskip_W, gat_W,
                                           tq_b, tk_b, tv_b, tskip_b);
    k_init<<<(NN * HDIM + 255) / 256, 256>>>();

    // big fused projection GEMM: [NN,128] @ [128,2304]
    sgemm128<<<dim3(PC / 128, (NN + 127) / 128), 256>>>(x, p_wcat, p_bcat, p_proj, NN, PC, DD);

    // SAGE neighbor mean
    k_sage_agg<<<(NE * DD + 255) / 256, 256>>>(ei, x);
    k_sage_mean<<<(NN * DD + 255) / 256, 256>>>();
    sgemm128<<<dim3(1, (NN + 127) / 128), 256>>>(p_mean, sage_Wl, sage_b, p_ms, NN, DD, DD);

    // GAT per-node attention coefficients
    k_gat_coef<<<NN, 128>>>(att_src, att_dst);

    // Transformer softmax-aggregate
    k_t_logits<<<NE / 8, 256>>>(ei, ea, te_W);
    k_t_expsum<<<(NE * NH + 255) / 256, 256>>>(ei);
    k_t_agg<<<NE / 8, 256>>>(ei, ea, te_W);

    // GAT softmax-aggregate (self loops handled in logits/expsum + fuse)
    k_g_logits<<<((NE + NN) * NH + 255) / 256, 256>>>(ei);
    k_g_expsum<<<((NE + NN) * NH + 255) / 256, 256>>>(ei);
    k_g_agg<<<NE / 8, 256>>>(ei);

    // gated fusion concat
    k_fuse_cat<<<(NN * DD + 255) / 256, 256>>>(gat_bias, gshort, gattn, gnb);

    // fusion GEMM: [NN,384] @ [384,128]
    sgemm128<<<dim3(1, (NN + 127) / 128), 256>>>(p_cat, fus_W, fus_b, p_fus, NN, DD, 3 * DD);

    // LN -> relu -> residual -> LN
    k_final<<<NN, 128>>>(x, fus_g, fus_beta, norm_g, norm_b, out);
}

// round 3
// speedup vs baseline: 1.1177x; 1.1177x over previous
#include <cuda_runtime.h>
#include <math.h>

#define NN 50000
#define NE 150000
#define DD 128
#define NH 4
#define EDIM 16
#define PC 2304
#define OFF_XR 0
#define OFF_Q 128
#define OFF_K 640
#define OFF_V 1152
#define OFF_SK 1664
#define OFF_G 1792

// ---------------- scratch (static device globals) ----------------
__device__ float g_proj[(size_t)NN * PC];      // xr | q | k | v | skip | g
__device__ float g_wcat[DD * PC];
__device__ float g_bcat[PC];
__device__ float g_mean[NN * DD];
__device__ float g_ms[NN * DD];
__device__ float g_as[NN * NH];
__device__ float g_ad[NN * NH];
__device__ float g_logT[(size_t)NE * NH];      // logits by CSR position
__device__ float g_cat[(size_t)NN * 3 * DD];
__device__ float g_fus[NN * DD];
// CSR
__device__ int g_deg[NN];
__device__ int g_ptr[NN + 1];
__device__ int g_pos[NN];
__device__ int g_eidx[NE];

// ---------------- helpers ----------------
__device__ __forceinline__ float warpSum(float v) {
#pragma unroll
    for (int o = 16; o; o >>= 1) v += __shfl_xor_sync(0xffffffffu, v, o);
    return v;
}
__device__ __forceinline__ float blockSum128(float v) {
    __shared__ float red[4];
    v = warpSum(v);
    int w = threadIdx.x >> 5;
    if ((threadIdx.x & 31) == 0) red[w] = v;
    __syncthreads();
    float r = red[0] + red[1] + red[2] + red[3];
    __syncthreads();
    return r;
}
__device__ __forceinline__ float sigm(float x) { return 1.f / (1.f + expf(-x)); }

// ---------------- CSR build ----------------
__global__ void k_zero_deg() {
    int t = blockIdx.x * blockDim.x + threadIdx.x;
    if (t < NN) g_deg[t] = 0;
}
__global__ void k_hist(const int* __restrict__ ei) {
    int e = blockIdx.x * blockDim.x + threadIdx.x;
    if (e < NE) atomicAdd(&g_deg[ei[NE + e]], 1);
}
__global__ void k_scan() {
    __shared__ int sm[1024];
    int run = 0;
    for (int base = 0; base < NN; base += 1024) {
        int i = base + threadIdx.x;
        int v = (i < NN) ? g_deg[i] : 0;
        sm[threadIdx.x] = v;
        __syncthreads();
#pragma unroll
        for (int off = 1; off < 1024; off <<= 1) {
            int t = (threadIdx.x >= off) ? sm[threadIdx.x - off] : 0;
            __syncthreads();
            sm[threadIdx.x] += t;
            __syncthreads();
        }
        int incl = sm[threadIdx.x];
        if (i < NN) {
            int start = run + incl - v;
            g_ptr[i] = start;
            g_pos[i] = start;
        }
        run += sm[1023];
        __syncthreads();
    }
    if (threadIdx.x == 0) g_ptr[NN] = NE;
}
__global__ void k_scatter(const int* __restrict__ ei) {
    int e = blockIdx.x * blockDim.x + threadIdx.x;
    if (e < NE) {
        int dst = ei[NE + e];
        int p = atomicAdd(&g_pos[dst], 1);
        g_eidx[p] = e;
    }
}

// ---------------- weight packing ----------------
__global__ void k_pack(const float* __restrict__ Wr, const float* __restrict__ tq,
                       const float* __restrict__ tk, const float* __restrict__ tv,
                       const float* __restrict__ tsk, const float* __restrict__ gat,
                       const float* __restrict__ qb, const float* __restrict__ kb,
                       const float* __restrict__ vb, const float* __restrict__ skb) {
    int t = blockIdx.x * blockDim.x + threadIdx.x;
    if (t >= DD * PC) return;
    int r = t / PC, c = t % PC;
    float v;
    if (c < 128)       v = Wr[r * 128 + c];
    else if (c < 640)  v = tq[r * 512 + (c - 128)];
    else if (c < 1152) v = tk[r * 512 + (c - 640)];
    else if (c < 1664) v = tv[r * 512 + (c - 1152)];
    else if (c < 1792) v = tsk[r * 128 + (c - 1664)];
    else               v = gat[r * 512 + (c - 1792)];
    g_wcat[t] = v;
    if (r == 0) {
        float b;
        if (c < 128)       b = 0.f;
        else if (c < 640)  b = qb[c - 128];
        else if (c < 1152) b = kb[c - 640];
        else if (c < 1664) b = vb[c - 1152];
        else if (c < 1792) b = skb[c - 1664];
        else               b = 0.f;
        g_bcat[c] = b;
    }
}

// ---------------- SGEMM 128x128x8, 256 threads, 8x8 per thread ----------------
__global__ __launch_bounds__(256) void sgemm128(
    const float* __restrict__ A, const float* __restrict__ B,
    const float* __restrict__ bias, float* __restrict__ C,
    int M, int Ncol, int K) {
    __shared__ float As[8][128];
    __shared__ float Bs[8][128];
    int tid = threadIdx.x;
    int tcol = tid & 15;
    int trow = tid >> 4;
    int rowBase = blockIdx.y * 128;
    int colBase = blockIdx.x * 128;
    float acc[8][8];
#pragma unroll
    for (int i = 0; i < 8; i++)
#pragma unroll
        for (int j = 0; j < 8; j++) acc[i][j] = 0.f;

    int aRow = tid >> 1;
    int aCol4 = (tid & 1) * 4;
    int bRow = tid >> 5;
    int bCol4 = (tid & 31) * 4;

    for (int k0 = 0; k0 < K; k0 += 8) {
        int gr = rowBase + aRow;
        float4 av = make_float4(0.f, 0.f, 0.f, 0.f);
        if (gr < M) av = *reinterpret_cast<const float4*>(A + (size_t)gr * K + k0 + aCol4);
        As[aCol4 + 0][aRow] = av.x;
        As[aCol4 + 1][aRow] = av.y;
        As[aCol4 + 2][aRow] = av.z;
        As[aCol4 + 3][aRow] = av.w;
        float4 bv = *reinterpret_cast<const float4*>(B + (size_t)(k0 + bRow) * Ncol + colBase + bCol4);
        *reinterpret_cast<float4*>(&Bs[bRow][bCol4]) = bv;
        __syncthreads();
#pragma unroll
        for (int kk = 0; kk < 8; kk++) {
            float4 a0 = *reinterpret_cast<const float4*>(&As[kk][trow * 4]);
            float4 a1 = *reinterpret_cast<const float4*>(&As[kk][64 + trow * 4]);
            float4 b0 = *reinterpret_cast<const float4*>(&Bs[kk][tcol * 4]);
            float4 b1 = *reinterpret_cast<const float4*>(&Bs[kk][64 + tcol * 4]);
            float a[8] = {a0.x, a0.y, a0.z, a0.w, a1.x, a1.y, a1.z, a1.w};
            float b[8] = {b0.x, b0.y, b0.z, b0.w, b1.x, b1.y, b1.z, b1.w};
#pragma unroll
            for (int i = 0; i < 8; i++)
#pragma unroll
                for (int j = 0; j < 8; j++) acc[i][j] += a[i] * b[j];
        }
        __syncthreads();
    }
#pragma unroll
    for (int i = 0; i < 8; i++) {
        int lr = (i < 4) ? (trow * 4 + i) : (64 + trow * 4 + i - 4);
        int gr = rowBase + lr;
        if (gr >= M) continue;
#pragma unroll
        for (int j = 0; j < 8; j++) {
            int lc = (j < 4) ? (tcol * 4 + j) : (64 + tcol * 4 + j - 4);
            int gc = colBase + lc;
            float v = acc[i][j];
            if (bias) v += bias[gc];
            C[(size_t)gr * Ncol + gc] = v;
        }
    }
}

// ---------------- SAGE gather mean (warp per dst) ----------------
__global__ __launch_bounds__(256) void k_sage2(const int* __restrict__ ei,
                                               const float* __restrict__ x) {
    int w = (blockIdx.x * 256 + threadIdx.x) >> 5;
    int lane = threadIdx.x & 31;
    if (w >= NN) return;
    int s = g_ptr[w], e1 = g_ptr[w + 1];
    float a0 = 0.f, a1 = 0.f, a2 = 0.f, a3 = 0.f;
    for (int j = s; j < e1; j++) {
        int src = ei[g_eidx[j]];
        const float* xr = x + (size_t)src * DD;
        a0 += xr[lane];
        a1 += xr[lane + 32];
        a2 += xr[lane + 64];
        a3 += xr[lane + 96];
    }
    float inv = 1.f / fmaxf((float)(e1 - s), 1.f);
    float* mr = g_mean + (size_t)w * DD;
    mr[lane] = a0 * inv;
    mr[lane + 32] = a1 * inv;
    mr[lane + 64] = a2 * inv;
    mr[lane + 96] = a3 * inv;
}

// ---------------- GAT attention coefficients ----------------
__global__ void k_gat_coef(const float* __restrict__ att_src, const float* __restrict__ att_dst) {
    int n = blockIdx.x;
    int w = threadIdx.x >> 5, lane = threadIdx.x & 31;
    const float* grow = g_proj + (size_t)n * PC + OFF_G + w * DD;
    float s1 = 0.f, s2 = 0.f;
    for (int d = lane; d < DD; d += 32) {
        float gv = grow[d];
        s1 += gv * att_src[w * DD + d];
        s2 += gv * att_dst[w * DD + d];
    }
    s1 = warpSum(s1);
    s2 = warpSum(s2);
    if (lane == 0) { g_as[n * NH + w] = s1; g_ad[n * NH + w] = s2; }
}

// ---------------- Transformer: per-dst (block=128, warp per head) ----------------
__global__ __launch_bounds__(128) void k_t_dst(const int* __restrict__ ei,
                                               const float* __restrict__ ea,
                                               const float* __restrict__ teW,
                                               const float* __restrict__ gattn) {
    __shared__ float ws[EDIM * NH * DD];
    __shared__ float hsum[NH][DD];
    for (int i = threadIdx.x; i < EDIM * NH * DD; i += 128) ws[i] = teW[i];
    __syncthreads();
    int h = threadIdx.x >> 5, lane = threadIdx.x & 31;
    float ga = sigm(gattn[0]);
    const float scale = 0.08838834764831845f;  // 1/sqrt(128)

    for (int n = blockIdx.x; n < NN; n += gridDim.x) {
        int s = g_ptr[n], e1 = g_ptr[n + 1];
        const float* prow = g_proj + (size_t)n * PC;
        float q0 = prow[OFF_Q + h * DD + lane];
        float q1 = prow[OFF_Q + h * DD + lane + 32];
        float q2 = prow[OFF_Q + h * DD + lane + 64];
        float q3 = prow[OFF_Q + h * DD + lane + 96];

        // pass 1: logits + online softmax max/sum
        float m = -1e30f, ssum = 0.f;
        for (int j = s; j < e1; j++) {
            int e = g_eidx[j];
            int src = ei[e];
            float eav = (lane < EDIM) ? ea[(size_t)e * EDIM + lane] : 0.f;
            const float* krow = g_proj + (size_t)src * PC + OFF_K + h * DD;
            float dot = 0.f;
#pragma unroll
            for (int k2 = 0; k2 < 4; k2++) {
                int c = h * DD + lane + 32 * k2;
                float ev = 0.f;
#pragma unroll
                for (int j2 = 0; j2 < EDIM; j2++)
                    ev += __shfl_sync(0xffffffffu, eav, j2) * ws[j2 * (NH * DD) + c];
                float qv = (k2 == 0) ? q0 : (k2 == 1) ? q1 : (k2 == 2) ? q2 : q3;
                dot += qv * (krow[lane + 32 * k2] + ev);
            }
            dot = warpSum(dot) * scale;
            if (lane == 0) g_logT[(size_t)j * NH + h] = dot;
            float mNew = fmaxf(m, dot);
            ssum = ssum * expf(m - mNew) + expf(dot - mNew);
            m = mNew;
        }
        __syncwarp();

        // pass 2: weighted aggregate
        float a0 = 0.f, a1 = 0.f, a2 = 0.f, a3 = 0.f;
        float denom = 1.f / (ssum + 1e-16f);
        for (int j = s; j < e1; j++) {
            int e = g_eidx[j];
            int src = ei[e];
            float alpha = expf(g_logT[(size_t)j * NH + h] - m) * denom;
            float eav = (lane < EDIM) ? ea[(size_t)e * EDIM + lane] : 0.f;
            const float* vrow = g_proj + (size_t)src * PC + OFF_V + h * DD;
#pragma unroll
            for (int k2 = 0; k2 < 4; k2++) {
                int c = h * DD + lane + 32 * k2;
                float ev = 0.f;
#pragma unroll
                for (int j2 = 0; j2 < EDIM; j2++)
                    ev += __shfl_sync(0xffffffffu, eav, j2) * ws[j2 * (NH * DD) + c];
                float contrib = (vrow[lane + 32 * k2] + ev) * alpha;
                if (k2 == 0) a0 += contrib;
                else if (k2 == 1) a1 += contrib;
                else if (k2 == 2) a2 += contrib;
                else a3 += contrib;
            }
        }
        hsum[h][lane] = a0;
        hsum[h][lane + 32] = a1;
        hsum[h][lane + 64] = a2;
        hsum[h][lane + 96] = a3;
        __syncthreads();
        int d = threadIdx.x;
        float sT = hsum[0][d] + hsum[1][d] + hsum[2][d] + hsum[3][d];
        float xa = fmaxf(sT * 0.25f + prow[OFF_SK + d], 0.f);
        g_cat[(size_t)n * 384 + 128 + d] = xa * ga;
        __syncthreads();
    }
}

// ---------------- GAT: per-dst (block=128, warp per head) ----------------
__global__ __launch_bounds__(128) void k_g_dst(const int* __restrict__ ei,
                                               const float* __restrict__ gat_bias,
                                               const float* __restrict__ gnb) {
    __shared__ float hsum[NH][DD];
    int h = threadIdx.x >> 5, lane = threadIdx.x & 31;
    float gn = sigm(gnb[0]);
    for (int n = blockIdx.x; n < NN; n += gridDim.x) {
        int s = g_ptr[n], e1 = g_ptr[n + 1];
        float ad = g_ad[n * NH + h];
        float lgSelf = g_as[n * NH + h] + ad;
        lgSelf = (lgSelf > 0.f) ? lgSelf : 0.2f * lgSelf;
        // max
        float m = lgSelf;
        for (int j = s; j < e1; j++) {
            int src = ei[g_eidx[j]];
            float lg = g_as[src * NH + h] + ad;
            lg = (lg > 0.f) ? lg : 0.2f * lg;
            m = fmaxf(m, lg);
        }
        // sum
        float ssum = expf(lgSelf - m);
        for (int j = s; j < e1; j++) {
            int src = ei[g_eidx[j]];
            float lg = g_as[src * NH + h] + ad;
            lg = (lg > 0.f) ? lg : 0.2f * lg;
            ssum += expf(lg - m);
        }
        float denom = 1.f / (ssum + 1e-16f);
        // aggregate (self + edges)
        float aself = expf(lgSelf - m) * denom;
        const float* gr = g_proj + (size_t)n * PC + OFF_G + h * DD;
        float a0 = gr[lane] * aself;
        float a1 = gr[lane + 32] * aself;
        float a2 = gr[lane + 64] * aself;
        float a3 = gr[lane + 96] * aself;
        for (int j = s; j < e1; j++) {
            int src = ei[g_eidx[j]];
            float lg = g_as[src * NH + h] + ad;
            lg = (lg > 0.f) ? lg : 0.2f * lg;
            float alpha = expf(lg - m) * denom;
            const float* grs = g_proj + (size_t)src * PC + OFF_G + h * DD;
            a0 += grs[lane] * alpha;
            a1 += grs[lane + 32] * alpha;
            a2 += grs[lane + 64] * alpha;
            a3 += grs[lane + 96] * alpha;
        }
        hsum[h][lane] = a0;
        hsum[h][lane + 32] = a1;
        hsum[h][lane + 64] = a2;
        hsum[h][lane + 96] = a3;
        __syncthreads();
        int d = threadIdx.x;
        float sG = hsum[0][d] + hsum[1][d] + hsum[2][d] + hsum[3][d];
        float xn = fmaxf(sG * 0.25f + gat_bias[d], 0.f);
        g_cat[(size_t)n * 384 + 256 + d] = xn * gn;
        __syncthreads();
    }
}

// ---------------- SAGE branch into g_cat ----------------
__global__ void k_fuse_sage(const float* __restrict__ gshort) {
    int t = blockIdx.x * blockDim.x + threadIdx.x;
    if (t >= NN * DD) return;
    int n = t >> 7, d = t & 127;
    float gs = sigm(gshort[0]);
    float xs = fmaxf(g_ms[t] + g_proj[(size_t)n * PC + OFF_XR + d], 0.f);
    g_cat[(size_t)n * 384 + d] = xs * gs;
}

// ---------------- final: LN -> relu -> residual -> LN ----------------
__global__ void k_final(const float* __restrict__ x,
                        const float* __restrict__ fus_g, const float* __restrict__ fus_b,
                        const float* __restrict__ norm_g, const float* __restrict__ norm_b,
                        float* __restrict__ out) {
    int n = blockIdx.x, d = threadIdx.x;
    float v = g_fus[n * DD + d];
    float m = blockSum128(v) * (1.f / 128.f);
    float c = v - m;
    float var = blockSum128(c * c) * (1.f / 128.f);
    float f = c * rsqrtf(var + 1e-5f) * fus_g[d] + fus_b[d];
    f = fmaxf(f, 0.f);
    float tsum = x[(size_t)n * DD + d] + f;
    float m2 = blockSum128(tsum) * (1.f / 128.f);
    float c2 = tsum - m2;
    float var2 = blockSum128(c2 * c2) * (1.f / 128.f);
    out[(size_t)n * DD + d] = c2 * rsqrtf(var2 + 1e-5f) * norm_g[d] + norm_b[d];
}

// ---------------- launcher ----------------
extern "C" void kernel_launch(void* const* d_in, const int* in_sizes, int n_in,
                              void* d_out, int out_size) {
    const float* x        = (const float*)d_in[0];
    const int*   ei       = (const int*)d_in[1];
    const float* ea       = (const float*)d_in[2];
    const float* sage_Wl  = (const float*)d_in[3];
    const float* sage_Wr  = (const float*)d_in[4];
    const float* sage_b   = (const float*)d_in[5];
    const float* tq_W     = (const float*)d_in[6];
    const float* tq_b     = (const float*)d_in[7];
    const float* tk_W     = (const float*)d_in[8];
    const float* tk_b     = (const float*)d_in[9];
    const float* tv_W     = (const float*)d_in[10];
    const float* tv_b     = (const float*)d_in[11];
    const float* te_W     = (const float*)d_in[12];
    const float* tskip_W  = (const float*)d_in[13];
    const float* tskip_b  = (const float*)d_in[14];
    const float* gat_W    = (const float*)d_in[15];
    const float* att_src  = (const float*)d_in[16];
    const float* att_dst  = (const float*)d_in[17];
    const float* gat_bias = (const float*)d_in[18];
    const float* gshort   = (const float*)d_in[19];
    const float* gattn    = (const float*)d_in[20];
    const float* gnb      = (const float*)d_in[21];
    const float* fus_W    = (const float*)d_in[22];
    const float* fus_b    = (const float*)d_in[23];
    const float* fus_g    = (const float*)d_in[24];
    const float* fus_beta = (const float*)d_in[25];
    const float* norm_g   = (const float*)d_in[26];
    const float* norm_b   = (const float*)d_in[27];
    float* out = (float*)d_out;

    float *p_proj, *p_wcat, *p_bcat, *p_mean, *p_ms, *p_cat, *p_fus;
    cudaGetSymbolAddress((void**)&p_proj, g_proj);
    cudaGetSymbolAddress((void**)&p_wcat, g_wcat);
    cudaGetSymbolAddress((void**)&p_bcat, g_bcat);
    cudaGetSymbolAddress((void**)&p_mean, g_mean);
    cudaGetSymbolAddress((void**)&p_ms, g_ms);
    cudaGetSymbolAddress((void**)&p_cat, g_cat);
    cudaGetSymbolAddress((void**)&p_fus, g_fus);

    // CSR build
    k_zero_deg<<<(NN + 255) / 256, 256>>>();
    k_hist<<<(NE + 255) / 256, 256>>>(ei);
    k_scan<<<1, 1024>>>();
    k_scatter<<<(NE + 255) / 256, 256>>>(ei);

    // weights + big fused projection GEMM: [NN,128] @ [128,2304]
    k_pack<<<(DD * PC + 255) / 256, 256>>>(sage_Wr, tq_W, tk_W, tv_W, tskip_W, gat_W,
                                           tq_b, tk_b, tv_b, tskip_b);
    sgemm128<<<dim3(PC / 128, (NN + 127) / 128), 256>>>(x, p_wcat, p_bcat, p_proj, NN, PC, DD);

    // SAGE neighbor mean (gather) + mean @ Wl
    k_sage2<<<(NN * 32 + 255) / 256, 256>>>(ei, x);
    sgemm128<<<dim3(1, (NN + 127) / 128), 256>>>(p_mean, sage_Wl, sage_b, p_ms, NN, DD, DD);

    // GAT per-node attention coefficients
    k_gat_coef<<<NN, 128>>>(att_src, att_dst);

    // per-dst softmax-aggregate kernels (no atomics)
    k_t_dst<<<1024, 128>>>(ei, ea, te_W, gattn);
    k_g_dst<<<2048, 128>>>(ei, gat_bias, gnb);

    // SAGE branch into g_cat
    k_fuse_sage<<<(NN * DD + 255) / 256, 256>>>(gshort);

    // fusion GEMM: [NN,384] @ [384,128]
    sgemm128<<<dim3(1, (NN + 127) / 128), 256>>>(p_cat, fus_W, fus_b, p_fus, NN, DD, 3 * DD);

    // LN -> relu -> residual -> LN
    k_final<<<NN, 128>>>(x, fus_g, fus_beta, norm_g, norm_b, out);
}